// round 9
// baseline (speedup 1.0000x reference)
#include <cuda_runtime.h>
#include <cstdint>

typedef unsigned long long u64;

#define PHI_F     1.6180339887498949f
#define INV_PHI_F 0.6180339887498949f

// ---------- packed f32x2 helpers (Blackwell FFMA2 path) ----------
__device__ __forceinline__ u64 pk2(float a, float b) {
    u64 r; asm("mov.b64 %0, {%1, %2};" : "=l"(r) : "f"(a), "f"(b)); return r;
}
__device__ __forceinline__ void upk2(u64 v, float& a, float& b) {
    asm("mov.b64 {%0, %1}, %2;" : "=f"(a), "=f"(b) : "l"(v));
}
__device__ __forceinline__ u64 ffma2(u64 a, u64 b, u64 c) {
    u64 d; asm("fma.rn.f32x2 %0, %1, %2, %3;" : "=l"(d) : "l"(a), "l"(b), "l"(c)); return d;
}

__device__ __forceinline__ float phi_spiral(float v) {
    // sigmoid(v/phi) * (v*phi / (1+|v|))
    float e = __expf(-v * INV_PHI_F);
    float s = __fdividef(1.0f, 1.0f + e);
    float t = __fdividef(v * PHI_F, 1.0f + fabsf(v));
    return s * t;
}

// Shared layout (in floats). Pair-packed weights: pairs over OUTPUT index.
//  s1 : [256][25] float2  layer1 W pairs  (j pairs, pad j=49 -> 0)   6400 f2
//  s2 : [49][25]  float2  layer2 Wn pairs (kh pairs, pad)            1225 f2
//  s3 : [49][11]  float2  layer3 W_int pairs (pad 21->22)             539 f2
//  sb1[50], sb2[50], sb3[22], sg[21], sbt[21], sW4[84], sb4[4]
#define S1_OFF   0
#define S2_OFF   12800
#define S3_OFF   15250
#define SB1_OFF  16328
#define SB2_OFF  16378
#define SB3_OFF  16428
#define SG_OFF   16450
#define SBT_OFF  16471
#define SW4_OFF  16492
#define SB4_OFF  16576
#define SMEM_FLOATS 16580
#define SMEM_BYTES  (SMEM_FLOATS * 4)

__global__ void __launch_bounds__(256)
seven_neurons_kernel(const float* __restrict__ x,
                     const float* __restrict__ W_in,  const float* __restrict__ b_in,
                     const float* __restrict__ Wn,    const float* __restrict__ bn,
                     const float* __restrict__ W_int, const float* __restrict__ b_int,
                     const float* __restrict__ gamma, const float* __restrict__ beta,
                     const float* __restrict__ W_out, const float* __restrict__ b_out,
                     float* __restrict__ out, int B)
{
    extern __shared__ float smem[];
    float2* s1 = (float2*)(smem + S1_OFF);
    float2* s2 = (float2*)(smem + S2_OFF);
    float2* s3 = (float2*)(smem + S3_OFF);
    float*  sb1 = smem + SB1_OFF;
    float*  sb2 = smem + SB2_OFF;
    float*  sb3 = smem + SB3_OFF;
    float*  sg  = smem + SG_OFF;
    float*  sbt = smem + SBT_OFF;
    float*  sW4 = smem + SW4_OFF;
    float*  sb4 = smem + SB4_OFF;

    const int tid = threadIdx.x;
    const int nthr = blockDim.x;

    // ---- stage weights into shared (pair-packed along output dim) ----
    for (int idx = tid; idx < 256 * 25; idx += nthr) {
        int k = idx / 25, p = idx % 25;
        int j0 = 2 * p;
        float a = W_in[j0 * 256 + k];
        float b = (j0 + 1 < 49) ? W_in[(j0 + 1) * 256 + k] : 0.0f;
        s1[idx] = make_float2(a, b);
    }
    for (int idx = tid; idx < 49 * 25; idx += nthr) {
        int i = idx / 25, p = idx % 25;
        int j0 = 2 * p;
        float a = Wn[j0 * 49 + i];
        float b = (j0 + 1 < 49) ? Wn[(j0 + 1) * 49 + i] : 0.0f;
        s2[idx] = make_float2(a, b);
    }
    for (int idx = tid; idx < 49 * 11; idx += nthr) {
        int i = idx / 11, p = idx % 11;
        int j0 = 2 * p;
        float a = W_int[j0 * 49 + i];
        float b = (j0 + 1 < 21) ? W_int[(j0 + 1) * 49 + i] : 0.0f;
        s3[idx] = make_float2(a, b);
    }
    for (int idx = tid; idx < 50; idx += nthr) sb1[idx] = (idx < 49) ? b_in[idx] : 0.0f;
    for (int idx = tid; idx < 50; idx += nthr) sb2[idx] = (idx < 49) ? bn[idx]   : 0.0f;
    for (int idx = tid; idx < 22; idx += nthr) sb3[idx] = (idx < 21) ? b_int[idx]: 0.0f;
    for (int idx = tid; idx < 21; idx += nthr) { sg[idx] = gamma[idx]; sbt[idx] = beta[idx]; }
    for (int idx = tid; idx < 84; idx += nthr) sW4[idx] = W_out[idx];
    for (int idx = tid; idx < 4;  idx += nthr) sb4[idx] = b_out[idx];
    __syncthreads();

    const int r = blockIdx.x * nthr + tid;
    if (r >= B) return;

    const u64* s1q = (const u64*)s1;
    const u64* s2q = (const u64*)s2;
    const u64* s3q = (const u64*)s3;

    // ================= Layer 1: [256] -> 49, pair-packed over j =================
    u64 acc[25];
#pragma unroll
    for (int p = 0; p < 25; p++) acc[p] = pk2(sb1[2 * p], sb1[2 * p + 1]);

    const float4* xr = (const float4*)(x + (size_t)r * 256);
#pragma unroll 4
    for (int k0 = 0; k0 < 64; k0++) {          // 64 float4 chunks = 256 k
        float4 xv = xr[k0];
        float xs[4] = {xv.x, xv.y, xv.z, xv.w};
#pragma unroll
        for (int kk = 0; kk < 4; kk++) {
            u64 xp = pk2(xs[kk], xs[kk]);
            const u64* wrow = s1q + (k0 * 4 + kk) * 25;
#pragma unroll
            for (int p = 0; p < 25; p++)
                acc[p] = ffma2(xp, wrow[p], acc[p]);
        }
    }

    float h[50];
#pragma unroll
    for (int p = 0; p < 25; p++) upk2(acc[p], h[2 * p], h[2 * p + 1]);
#pragma unroll
    for (int j = 0; j < 49; j++) h[j] = phi_spiral(h[j]);

    // ================= Layer 2: 49 -> 49 (7 parallel 49->7), pair-packed =================
    u64 acc2[25];
#pragma unroll
    for (int p = 0; p < 25; p++) acc2[p] = pk2(sb2[2 * p], sb2[2 * p + 1]);
#pragma unroll
    for (int i = 0; i < 49; i++) {
        u64 hp = pk2(h[i], h[i]);
        const u64* wrow = s2q + i * 25;
#pragma unroll
        for (int p = 0; p < 25; p++)
            acc2[p] = ffma2(hp, wrow[p], acc2[p]);
    }

    float c[50];
#pragma unroll
    for (int p = 0; p < 25; p++) upk2(acc2[p], c[2 * p], c[2 * p + 1]);
#pragma unroll
    for (int j = 0; j < 49; j++) c[j] = phi_spiral(c[j]);

    // ================= Layer 3: 49 -> 21, pair-packed =================
    u64 acc3[11];
#pragma unroll
    for (int p = 0; p < 11; p++) acc3[p] = pk2(sb3[2 * p], sb3[2 * p + 1]);
#pragma unroll
    for (int i = 0; i < 49; i++) {
        u64 cp = pk2(c[i], c[i]);
        const u64* wrow = s3q + i * 11;
#pragma unroll
        for (int p = 0; p < 11; p++)
            acc3[p] = ffma2(cp, wrow[p], acc3[p]);
    }

    float ig[22];
#pragma unroll
    for (int p = 0; p < 11; p++) upk2(acc3[p], ig[2 * p], ig[2 * p + 1]);
#pragma unroll
    for (int j = 0; j < 21; j++) ig[j] = phi_spiral(ig[j]);

    // ================= LayerNorm over 21 =================
    float mu = 0.0f;
#pragma unroll
    for (int j = 0; j < 21; j++) mu += ig[j];
    mu *= (1.0f / 21.0f);
    float var = 0.0f;
#pragma unroll
    for (int j = 0; j < 21; j++) { float d = ig[j] - mu; var += d * d; }
    var *= (1.0f / 21.0f);
    float inv = rsqrtf(var + 1e-5f);
    float nrm[21];
#pragma unroll
    for (int j = 0; j < 21; j++) nrm[j] = (ig[j] - mu) * inv * sg[j] + sbt[j];

    // ================= Layer 4: 21 -> 4 =================
    float o0 = sb4[0], o1 = sb4[1], o2 = sb4[2], o3 = sb4[3];
#pragma unroll
    for (int j = 0; j < 21; j++) {
        float v = nrm[j];
        o0 = fmaf(v, sW4[0 * 21 + j], o0);
        o1 = fmaf(v, sW4[1 * 21 + j], o1);
        o2 = fmaf(v, sW4[2 * 21 + j], o2);
        o3 = fmaf(v, sW4[3 * 21 + j], o3);
    }
    float4 ov = make_float4(o0, o1, o2, o3);
    *(float4*)(out + (size_t)r * 4) = ov;
}

extern "C" void kernel_launch(void* const* d_in, const int* in_sizes, int n_in,
                              void* d_out, int out_size)
{
    const float* x     = (const float*)d_in[0];
    const float* W_in  = (const float*)d_in[1];
    const float* b_in  = (const float*)d_in[2];
    const float* Wn    = (const float*)d_in[3];
    const float* bn    = (const float*)d_in[4];
    const float* W_int = (const float*)d_in[5];
    const float* b_int = (const float*)d_in[6];
    const float* gamma = (const float*)d_in[7];
    const float* beta  = (const float*)d_in[8];
    const float* W_out = (const float*)d_in[9];
    const float* b_out = (const float*)d_in[10];
    float* out = (float*)d_out;

    int B = in_sizes[0] / 256;

    cudaFuncSetAttribute(seven_neurons_kernel,
                         cudaFuncAttributeMaxDynamicSharedMemorySize, SMEM_BYTES);

    int threads = 256;
    int blocks = (B + threads - 1) / threads;
    seven_neurons_kernel<<<blocks, threads, SMEM_BYTES>>>(
        x, W_in, b_in, Wn, bn, W_int, b_int, gamma, beta, W_out, b_out, out, B);
}

// round 13
// speedup vs baseline: 1.0934x; 1.0934x over previous
#include <cuda_runtime.h>
#include <cstdint>

typedef unsigned long long u64;

#define PHI_F     1.6180339887498949f
#define INV_PHI_F 0.6180339887498949f

__device__ __forceinline__ u64 pk2(float a, float b) {
    u64 r; asm("mov.b64 %0, {%1, %2};" : "=l"(r) : "f"(a), "f"(b)); return r;
}
__device__ __forceinline__ void upk2(u64 v, float& a, float& b) {
    asm("mov.b64 {%0, %1}, %2;" : "=f"(a), "=f"(b) : "l"(v));
}
__device__ __forceinline__ u64 ffma2(u64 a, u64 b, u64 c) {
    u64 d; asm("fma.rn.f32x2 %0, %1, %2, %3;" : "=l"(d) : "l"(a), "l"(b), "l"(c)); return d;
}

__device__ __forceinline__ float phi_spiral(float v) {
    float e = __expf(-v * INV_PHI_F);
    float s = __fdividef(1.0f, 1.0f + e);
    float t = __fdividef(v * PHI_F, 1.0f + fabsf(v));
    return s * t;
}

// Shared layout (floats). Weights packed as float4 along OUTPUT dim (quad = 2 f32x2 pairs):
//  s1: [256][13] float4  layer1 (49 outputs padded to 52)   13312 floats
//  s2: [49][13]  float4  layer2 (49 -> 52)                   2548
//  s3: [49][6]   float4  layer3 (21 -> 24)                   1176
#define S1_OFF   0
#define S2_OFF   13312
#define S3_OFF   15860
#define SB1_OFF  17036   // 52
#define SB2_OFF  17088   // 52
#define SB3_OFF  17140   // 24
#define SG_OFF   17164   // 21
#define SBT_OFF  17185   // 21
#define SW4_OFF  17206   // 84
#define SB4_OFF  17290   // 4
#define SMEM_FLOATS 17294
#define SMEM_BYTES  (SMEM_FLOATS * 4)

#define THREADS 128

__global__ void __launch_bounds__(THREADS, 3)
seven_neurons_kernel(const float* __restrict__ x,
                     const float* __restrict__ W_in,  const float* __restrict__ b_in,
                     const float* __restrict__ Wn,    const float* __restrict__ bn,
                     const float* __restrict__ W_int, const float* __restrict__ b_int,
                     const float* __restrict__ gamma, const float* __restrict__ beta,
                     const float* __restrict__ W_out, const float* __restrict__ b_out,
                     float* __restrict__ out, int B)
{
    extern __shared__ float smem[];
    float4* s1 = (float4*)(smem + S1_OFF);
    float4* s2 = (float4*)(smem + S2_OFF);
    float4* s3 = (float4*)(smem + S3_OFF);
    float*  sb1 = smem + SB1_OFF;
    float*  sb2 = smem + SB2_OFF;
    float*  sb3 = smem + SB3_OFF;
    float*  sg  = smem + SG_OFF;
    float*  sbt = smem + SBT_OFF;
    float*  sW4 = smem + SW4_OFF;
    float*  sb4 = smem + SB4_OFF;

    const int tid = threadIdx.x;

    // ---- stage weights: quad-packed along output dim ----
    for (int idx = tid; idx < 256 * 13; idx += THREADS) {
        int k = idx / 13, q = idx % 13;
        int j0 = 4 * q;
        float4 w;
        w.x = (j0 + 0 < 49) ? W_in[(j0 + 0) * 256 + k] : 0.0f;
        w.y = (j0 + 1 < 49) ? W_in[(j0 + 1) * 256 + k] : 0.0f;
        w.z = (j0 + 2 < 49) ? W_in[(j0 + 2) * 256 + k] : 0.0f;
        w.w = (j0 + 3 < 49) ? W_in[(j0 + 3) * 256 + k] : 0.0f;
        s1[idx] = w;
    }
    for (int idx = tid; idx < 49 * 13; idx += THREADS) {
        int i = idx / 13, q = idx % 13;
        int j0 = 4 * q;
        float4 w;
        w.x = (j0 + 0 < 49) ? Wn[(j0 + 0) * 49 + i] : 0.0f;
        w.y = (j0 + 1 < 49) ? Wn[(j0 + 1) * 49 + i] : 0.0f;
        w.z = (j0 + 2 < 49) ? Wn[(j0 + 2) * 49 + i] : 0.0f;
        w.w = (j0 + 3 < 49) ? Wn[(j0 + 3) * 49 + i] : 0.0f;
        s2[idx] = w;
    }
    for (int idx = tid; idx < 49 * 6; idx += THREADS) {
        int i = idx / 6, q = idx % 6;
        int j0 = 4 * q;
        float4 w;
        w.x = (j0 + 0 < 21) ? W_int[(j0 + 0) * 49 + i] : 0.0f;
        w.y = (j0 + 1 < 21) ? W_int[(j0 + 1) * 49 + i] : 0.0f;
        w.z = (j0 + 2 < 21) ? W_int[(j0 + 2) * 49 + i] : 0.0f;
        w.w = (j0 + 3 < 21) ? W_int[(j0 + 3) * 49 + i] : 0.0f;
        s3[idx] = w;
    }
    for (int idx = tid; idx < 52; idx += THREADS) sb1[idx] = (idx < 49) ? b_in[idx] : 0.0f;
    for (int idx = tid; idx < 52; idx += THREADS) sb2[idx] = (idx < 49) ? bn[idx]   : 0.0f;
    for (int idx = tid; idx < 24; idx += THREADS) sb3[idx] = (idx < 21) ? b_int[idx]: 0.0f;
    for (int idx = tid; idx < 21; idx += THREADS) { sg[idx] = gamma[idx]; sbt[idx] = beta[idx]; }
    for (int idx = tid; idx < 84; idx += THREADS) sW4[idx] = W_out[idx];
    for (int idx = tid; idx < 4;  idx += THREADS) sb4[idx] = b_out[idx];
    __syncthreads();

    const int r = blockIdx.x * THREADS + tid;
    if (r >= B) return;

    const ulonglong2* s1v = (const ulonglong2*)s1;  // .x = pair(4q,4q+1), .y = pair(4q+2,4q+3)
    const ulonglong2* s2v = (const ulonglong2*)s2;
    const ulonglong2* s3v = (const ulonglong2*)s3;

    // ================= Layer 1: 256 -> 49 (26 packed pairs, 13 LDS.128/k) =================
    u64 acc[26];
#pragma unroll
    for (int t = 0; t < 26; t++) acc[t] = pk2(sb1[2 * t], sb1[2 * t + 1]);

    const float4* xr = (const float4*)(x + (size_t)r * 256);
#pragma unroll 4
    for (int k0 = 0; k0 < 64; k0++) {
        float4 xv = xr[k0];
        float xs[4] = {xv.x, xv.y, xv.z, xv.w};
#pragma unroll
        for (int kk = 0; kk < 4; kk++) {
            u64 xp = pk2(xs[kk], xs[kk]);
            const ulonglong2* wrow = s1v + (k0 * 4 + kk) * 13;
#pragma unroll
            for (int q = 0; q < 13; q++) {
                ulonglong2 w = wrow[q];
                acc[2 * q]     = ffma2(xp, w.x, acc[2 * q]);
                acc[2 * q + 1] = ffma2(xp, w.y, acc[2 * q + 1]);
            }
        }
    }

    float h[52];
#pragma unroll
    for (int t = 0; t < 26; t++) upk2(acc[t], h[2 * t], h[2 * t + 1]);
#pragma unroll
    for (int j = 0; j < 49; j++) h[j] = phi_spiral(h[j]);

    // ================= Layer 2: 49 -> 49 =================
    u64 acc2[26];
#pragma unroll
    for (int t = 0; t < 26; t++) acc2[t] = pk2(sb2[2 * t], sb2[2 * t + 1]);
#pragma unroll
    for (int i = 0; i < 49; i++) {
        u64 hp = pk2(h[i], h[i]);
        const ulonglong2* wrow = s2v + i * 13;
#pragma unroll
        for (int q = 0; q < 13; q++) {
            ulonglong2 w = wrow[q];
            acc2[2 * q]     = ffma2(hp, w.x, acc2[2 * q]);
            acc2[2 * q + 1] = ffma2(hp, w.y, acc2[2 * q + 1]);
        }
    }

    float c[52];
#pragma unroll
    for (int t = 0; t < 26; t++) upk2(acc2[t], c[2 * t], c[2 * t + 1]);
#pragma unroll
    for (int j = 0; j < 49; j++) c[j] = phi_spiral(c[j]);

    // ================= Layer 3: 49 -> 21 =================
    u64 acc3[12];
#pragma unroll
    for (int t = 0; t < 12; t++) acc3[t] = pk2(sb3[2 * t], sb3[2 * t + 1]);
#pragma unroll
    for (int i = 0; i < 49; i++) {
        u64 cp = pk2(c[i], c[i]);
        const ulonglong2* wrow = s3v + i * 6;
#pragma unroll
        for (int q = 0; q < 6; q++) {
            ulonglong2 w = wrow[q];
            acc3[2 * q]     = ffma2(cp, w.x, acc3[2 * q]);
            acc3[2 * q + 1] = ffma2(cp, w.y, acc3[2 * q + 1]);
        }
    }

    float ig[24];
#pragma unroll
    for (int t = 0; t < 12; t++) upk2(acc3[t], ig[2 * t], ig[2 * t + 1]);
#pragma unroll
    for (int j = 0; j < 21; j++) ig[j] = phi_spiral(ig[j]);

    // ================= LayerNorm over 21 =================
    float mu = 0.0f;
#pragma unroll
    for (int j = 0; j < 21; j++) mu += ig[j];
    mu *= (1.0f / 21.0f);
    float var = 0.0f;
#pragma unroll
    for (int j = 0; j < 21; j++) { float d = ig[j] - mu; var += d * d; }
    var *= (1.0f / 21.0f);
    float inv = rsqrtf(var + 1e-5f);
    float nrm[21];
#pragma unroll
    for (int j = 0; j < 21; j++) nrm[j] = (ig[j] - mu) * inv * sg[j] + sbt[j];

    // ================= Layer 4: 21 -> 4 =================
    float o0 = sb4[0], o1 = sb4[1], o2 = sb4[2], o3 = sb4[3];
#pragma unroll
    for (int j = 0; j < 21; j++) {
        float v = nrm[j];
        o0 = fmaf(v, sW4[0 * 21 + j], o0);
        o1 = fmaf(v, sW4[1 * 21 + j], o1);
        o2 = fmaf(v, sW4[2 * 21 + j], o2);
        o3 = fmaf(v, sW4[3 * 21 + j], o3);
    }
    *(float4*)(out + (size_t)r * 4) = make_float4(o0, o1, o2, o3);
}

extern "C" void kernel_launch(void* const* d_in, const int* in_sizes, int n_in,
                              void* d_out, int out_size)
{
    const float* x     = (const float*)d_in[0];
    const float* W_in  = (const float*)d_in[1];
    const float* b_in  = (const float*)d_in[2];
    const float* Wn    = (const float*)d_in[3];
    const float* bn    = (const float*)d_in[4];
    const float* W_int = (const float*)d_in[5];
    const float* b_int = (const float*)d_in[6];
    const float* gamma = (const float*)d_in[7];
    const float* beta  = (const float*)d_in[8];
    const float* W_out = (const float*)d_in[9];
    const float* b_out = (const float*)d_in[10];
    float* out = (float*)d_out;

    int B = in_sizes[0] / 256;

    cudaFuncSetAttribute(seven_neurons_kernel,
                         cudaFuncAttributeMaxDynamicSharedMemorySize, SMEM_BYTES);

    int blocks = (B + THREADS - 1) / THREADS;
    seven_neurons_kernel<<<blocks, THREADS, SMEM_BYTES>>>(
        x, W_in, b_in, Wn, bn, W_int, b_int, gamma, beta, W_out, b_out, out, B);
}